// round 1
// baseline (speedup 1.0000x reference)
#include <cuda_runtime.h>
#include <math.h>

// Problem constants (B=8, H=W=128, C=384, window=8)
#define TOKENS   131072              // 8*128*128
#define CDIM     384
#define NQKV     1152
#define NWIN     2048                // 8 * 16 * 16 windows

// Scratch (allocation-free rule: __device__ globals)
__device__ float g_qkv[(size_t)TOKENS * NQKV];   // ~604 MB
__device__ float g_att[(size_t)TOKENS * CDIM];   // ~201 MB

// ---------------------------------------------------------------------------
// Generic SGEMM: C[M,N] = A[M,K] @ B[K,N] + bias[N]
// BM=BN=128, BK=8, 256 threads, 8x8 outputs/thread (4+4 split)
// ---------------------------------------------------------------------------
__global__ __launch_bounds__(256) void sgemm_bias(
    const float* __restrict__ A, const float* __restrict__ B,
    const float* __restrict__ bias, float* __restrict__ C,
    int Mdim, int Ndim, int Kdim)
{
    __shared__ float As[8][128];
    __shared__ float Bs[8][128];

    const int tid = threadIdx.x;
    const int m0 = blockIdx.y * 128;
    const int n0 = blockIdx.x * 128;
    const int tx = tid & 15;
    const int ty = tid >> 4;

    const int arow = tid >> 1;
    const int ak   = (tid & 1) * 4;
    const int brow = tid >> 5;
    const int bn   = (tid & 31) * 4;

    const float* Aptr = A + (size_t)(m0 + arow) * Kdim + ak;
    const float* Bptr = B + (size_t)brow * Ndim + n0 + bn;

    float acc[8][8];
#pragma unroll
    for (int i = 0; i < 8; i++)
#pragma unroll
        for (int j = 0; j < 8; j++) acc[i][j] = 0.f;

    for (int kt = 0; kt < Kdim; kt += 8) {
        float4 av = *(const float4*)Aptr;
        Aptr += 8;
        As[ak + 0][arow] = av.x;
        As[ak + 1][arow] = av.y;
        As[ak + 2][arow] = av.z;
        As[ak + 3][arow] = av.w;
        float4 bv = *(const float4*)Bptr;
        Bptr += (size_t)8 * Ndim;
        *(float4*)&Bs[brow][bn] = bv;
        __syncthreads();
#pragma unroll
        for (int k = 0; k < 8; k++) {
            float4 a0 = *(const float4*)&As[k][ty * 4];
            float4 a1 = *(const float4*)&As[k][ty * 4 + 64];
            float4 b0 = *(const float4*)&Bs[k][tx * 4];
            float4 b1 = *(const float4*)&Bs[k][tx * 4 + 64];
            float a[8] = {a0.x, a0.y, a0.z, a0.w, a1.x, a1.y, a1.z, a1.w};
            float b[8] = {b0.x, b0.y, b0.z, b0.w, b1.x, b1.y, b1.z, b1.w};
#pragma unroll
            for (int i = 0; i < 8; i++)
#pragma unroll
                for (int j = 0; j < 8; j++) acc[i][j] += a[i] * b[j];
        }
        __syncthreads();
    }

    float4 bia0 = *(const float4*)&bias[n0 + tx * 4];
    float4 bia1 = *(const float4*)&bias[n0 + tx * 4 + 64];
#pragma unroll
    for (int i = 0; i < 8; i++) {
        int r = m0 + ((i < 4) ? (ty * 4 + i) : (64 + ty * 4 + i - 4));
        float* crow = C + (size_t)r * Ndim + n0;
        float4 o0 = make_float4(acc[i][0] + bia0.x, acc[i][1] + bia0.y,
                                acc[i][2] + bia0.z, acc[i][3] + bia0.w);
        float4 o1 = make_float4(acc[i][4] + bia1.x, acc[i][5] + bia1.y,
                                acc[i][6] + bia1.z, acc[i][7] + bia1.w);
        *(float4*)(crow + tx * 4) = o0;
        *(float4*)(crow + 64 + tx * 4) = o1;
    }
}

// ---------------------------------------------------------------------------
// Per-window attention: block = one 8x8 window (64 tokens)
// S = Q K^T (64x64, K=384) -> softmax -> O = P V (64x384)
// Reads q/k/v rows from g_qkv (gather by token index), writes g_att in
// original token order (window-reverse is implicit).
// ---------------------------------------------------------------------------
__global__ __launch_bounds__(256) void window_attn()
{
    const int g   = blockIdx.x;      // [0, 2048)
    const int b   = g >> 8;          // 256 windows per image
    const int win = g & 255;
    const int wy  = win >> 4;
    const int wx  = win & 15;

    __shared__ int tok[64];
    __shared__ float Ss[64][65];                       // S then P (padded)
    __shared__ __align__(16) char raw[64 * 68 * 4];    // QK tiles / V tile overlay
    float (*Qs)[64] = (float(*)[64])raw;               // [32][64]  8KB
    float (*Ks)[64] = (float(*)[64])(raw + 8192);      // [32][64]  8KB
    float (*Vs)[68] = (float(*)[68])raw;               // [64][68]  17KB (overlays Q/K)

    const int tid = threadIdx.x;
    if (tid < 64) {
        int py = tid >> 3, px = tid & 7;
        tok[tid] = b * 16384 + (wy * 8 + py) * 128 + (wx * 8 + px);
    }
    __syncthreads();

    const int tx = tid & 15;
    const int ty = tid >> 4;
    const int lr = tid & 63;          // load row
    const int lk = (tid >> 6) * 8;    // load k-subgroup {0,8,16,24}

    // ---- Phase 1: S = Q K^T ----
    float acc[4][4];
#pragma unroll
    for (int i = 0; i < 4; i++)
#pragma unroll
        for (int j = 0; j < 4; j++) acc[i][j] = 0.f;

    const size_t rowbase = (size_t)tok[lr] * NQKV;
    for (int kt = 0; kt < CDIM; kt += 32) {
        const float* qrow = g_qkv + rowbase + kt + lk;
        float4 q0 = *(const float4*)qrow;
        float4 q1 = *(const float4*)(qrow + 4);
        const float* krow = qrow + CDIM;
        float4 k0 = *(const float4*)krow;
        float4 k1 = *(const float4*)(krow + 4);
        Qs[lk + 0][lr] = q0.x; Qs[lk + 1][lr] = q0.y;
        Qs[lk + 2][lr] = q0.z; Qs[lk + 3][lr] = q0.w;
        Qs[lk + 4][lr] = q1.x; Qs[lk + 5][lr] = q1.y;
        Qs[lk + 6][lr] = q1.z; Qs[lk + 7][lr] = q1.w;
        Ks[lk + 0][lr] = k0.x; Ks[lk + 1][lr] = k0.y;
        Ks[lk + 2][lr] = k0.z; Ks[lk + 3][lr] = k0.w;
        Ks[lk + 4][lr] = k1.x; Ks[lk + 5][lr] = k1.y;
        Ks[lk + 6][lr] = k1.z; Ks[lk + 7][lr] = k1.w;
        __syncthreads();
#pragma unroll
        for (int k = 0; k < 32; k++) {
            float4 a = *(const float4*)&Qs[k][ty * 4];
            float4 bb = *(const float4*)&Ks[k][tx * 4];
            float av[4] = {a.x, a.y, a.z, a.w};
            float bv[4] = {bb.x, bb.y, bb.z, bb.w};
#pragma unroll
            for (int i = 0; i < 4; i++)
#pragma unroll
                for (int j = 0; j < 4; j++) acc[i][j] += av[i] * bv[j];
        }
        __syncthreads();
    }
#pragma unroll
    for (int i = 0; i < 4; i++)
#pragma unroll
        for (int j = 0; j < 4; j++) Ss[ty * 4 + i][tx * 4 + j] = acc[i][j];
    __syncthreads();

    // ---- Phase 2: softmax rows (thread r handles row r) ----
    if (tid < 64) {
        float m = -1e30f;
#pragma unroll 8
        for (int j = 0; j < 64; j++) m = fmaxf(m, Ss[tid][j]);
        float s = 0.f;
#pragma unroll 8
        for (int j = 0; j < 64; j++) {
            float e = expf(Ss[tid][j] - m);
            Ss[tid][j] = e;
            s += e;
        }
        float inv = 1.f / s;
#pragma unroll 8
        for (int j = 0; j < 64; j++) Ss[tid][j] *= inv;
    }
    __syncthreads();

    // ---- Phase 3: O = P V (tile over C in chunks of 64) ----
    const int vc = (tid >> 6) * 16;   // V col subgroup {0,16,32,48}
    for (int ct = 0; ct < CDIM; ct += 64) {
        const float* vrow = g_qkv + rowbase + 2 * CDIM + ct + vc;
        float4 v0 = *(const float4*)(vrow);
        float4 v1 = *(const float4*)(vrow + 4);
        float4 v2 = *(const float4*)(vrow + 8);
        float4 v3 = *(const float4*)(vrow + 12);
        *(float4*)&Vs[lr][vc + 0]  = v0;
        *(float4*)&Vs[lr][vc + 4]  = v1;
        *(float4*)&Vs[lr][vc + 8]  = v2;
        *(float4*)&Vs[lr][vc + 12] = v3;
        __syncthreads();

        float o[4][4];
#pragma unroll
        for (int i = 0; i < 4; i++)
#pragma unroll
            for (int j = 0; j < 4; j++) o[i][j] = 0.f;
#pragma unroll
        for (int k = 0; k < 64; k++) {
            float a0 = Ss[ty * 4 + 0][k];
            float a1 = Ss[ty * 4 + 1][k];
            float a2 = Ss[ty * 4 + 2][k];
            float a3 = Ss[ty * 4 + 3][k];
            float4 bb = *(const float4*)&Vs[k][tx * 4];
            o[0][0] += a0 * bb.x; o[0][1] += a0 * bb.y; o[0][2] += a0 * bb.z; o[0][3] += a0 * bb.w;
            o[1][0] += a1 * bb.x; o[1][1] += a1 * bb.y; o[1][2] += a1 * bb.z; o[1][3] += a1 * bb.w;
            o[2][0] += a2 * bb.x; o[2][1] += a2 * bb.y; o[2][2] += a2 * bb.z; o[2][3] += a2 * bb.w;
            o[3][0] += a3 * bb.x; o[3][1] += a3 * bb.y; o[3][2] += a3 * bb.z; o[3][3] += a3 * bb.w;
        }
#pragma unroll
        for (int i = 0; i < 4; i++) {
            float* orow = g_att + (size_t)tok[ty * 4 + i] * CDIM + ct + tx * 4;
            *(float4*)orow = make_float4(o[i][0], o[i][1], o[i][2], o[i][3]);
        }
        __syncthreads();
    }
}

// ---------------------------------------------------------------------------
extern "C" void kernel_launch(void* const* d_in, const int* in_sizes, int n_in,
                              void* d_out, int out_size)
{
    const float* x      = (const float*)d_in[0];
    const float* w_qkv  = (const float*)d_in[1];
    const float* b_qkv  = (const float*)d_in[2];
    const float* w_proj = (const float*)d_in[3];
    const float* b_proj = (const float*)d_in[4];
    float* out = (float*)d_out;

    float* qkv_ptr = nullptr;
    float* att_ptr = nullptr;
    cudaGetSymbolAddress((void**)&qkv_ptr, g_qkv);
    cudaGetSymbolAddress((void**)&att_ptr, g_att);

    // K1: qkv = x @ w_qkv + b_qkv   [131072 x 1152]
    sgemm_bias<<<dim3(NQKV / 128, TOKENS / 128), 256>>>(
        x, w_qkv, b_qkv, qkv_ptr, TOKENS, NQKV, CDIM);

    // K2: per-window attention -> g_att (original token order)
    window_attn<<<NWIN, 256>>>();

    // K3: out = att @ w_proj + b_proj   [131072 x 384]
    sgemm_bias<<<dim3(CDIM / 128, TOKENS / 128), 256>>>(
        att_ptr, w_proj, b_proj, out, TOKENS, CDIM, CDIM);
}

// round 3
// speedup vs baseline: 1.6817x; 1.6817x over previous
#include <cuda_runtime.h>
#include <cuda_bf16.h>
#include <cstdint>
#include <math.h>

// Problem constants (B=8, H=W=128, C=384, window=8)
#define TOKENS   131072              // 8*128*128
#define CDIM     384
#define NQKV     1152
#define NWIN     2048                // 8 * 16 * 16 windows

// ---------------------------------------------------------------------------
// Scratch (allocation-free rule: __device__ globals)
// ---------------------------------------------------------------------------
__device__ float          g_qkv[(size_t)TOKENS * NQKV];    // fp32 qkv (604 MB)
__device__ float          g_att[(size_t)TOKENS * CDIM];    // fp32 attn out (201 MB)
__device__ __nv_bfloat16  g_Whi1[(size_t)NQKV * CDIM];     // w_qkv^T hi  [N][K]
__device__ __nv_bfloat16  g_Wlo1[(size_t)NQKV * CDIM];     // w_qkv^T lo
__device__ __nv_bfloat16  g_Whi3[(size_t)CDIM * CDIM];     // w_proj^T hi
__device__ __nv_bfloat16  g_Wlo3[(size_t)CDIM * CDIM];     // w_proj^T lo

__device__ __forceinline__ uint32_t smem_u32(const void* p) {
    uint32_t a;
    asm("{ .reg .u64 tmp; cvta.to.shared.u64 tmp, %1; cvt.u32.u64 %0, tmp; }"
        : "=r"(a) : "l"(p));
    return a;
}

// Split a float2 into packed bf16x2 hi and lo (residual) parts.
__device__ __forceinline__ void split2(float x, float y, uint32_t& hi, uint32_t& lo) {
    uint32_t h;
    asm("cvt.rn.bf16x2.f32 %0, %1, %2;" : "=r"(h) : "f"(y), "f"(x));
    float h0 = __uint_as_float(h << 16);
    float h1 = __uint_as_float(h & 0xffff0000u);
    float r0 = x - h0, r1 = y - h1;
    asm("cvt.rn.bf16x2.f32 %0, %1, %2;" : "=r"(lo) : "f"(r1), "f"(r0));
    hi = h;
}

__device__ __forceinline__ void mma16816(float* c, const uint32_t* a,
                                         uint32_t b0, uint32_t b1) {
    asm volatile(
        "mma.sync.aligned.m16n8k16.row.col.f32.bf16.bf16.f32 "
        "{%0,%1,%2,%3}, {%4,%5,%6,%7}, {%8,%9}, {%0,%1,%2,%3};\n"
        : "+f"(c[0]), "+f"(c[1]), "+f"(c[2]), "+f"(c[3])
        : "r"(a[0]), "r"(a[1]), "r"(a[2]), "r"(a[3]), "r"(b0), "r"(b1));
}

// ---------------------------------------------------------------------------
// Weight split + transpose: w [384 x N] fp32 -> Whi/Wlo [N x 384] bf16
// ---------------------------------------------------------------------------
__global__ __launch_bounds__(256) void split_w_kernel(
    const float* __restrict__ w, __nv_bfloat16* __restrict__ Whi,
    __nv_bfloat16* __restrict__ Wlo, int N)
{
    const int t = blockIdx.x * 256 + threadIdx.x;
    if (t >= N * CDIM) return;
    const int n = t / CDIM;
    const int k = t % CDIM;
    const float v = w[(size_t)k * N + n];
    __nv_bfloat16 h = __float2bfloat16(v);
    __nv_bfloat16 l = __float2bfloat16(v - __bfloat162float(h));
    Whi[(size_t)n * CDIM + k] = h;
    Wlo[(size_t)n * CDIM + k] = l;
}

// ---------------------------------------------------------------------------
// HMMA GEMM: C[M x Ndim] = A[M x 384](fp32, split in-reg) @ W^T + bias
//   BM=128, BN=128, BK=32, 256 threads (8 warps: 4(M) x 2(N)).
//   A: direct gmem fragment loads (float2) -> reg split to bf16 hi/lo.
//   B: bf16 hi/lo planes, cp.async double-buffered smem, 40-elem row stride.
//   3 mma passes per fragment: hi*hi + lo*hi + hi*lo (fp32 accum).
// ---------------------------------------------------------------------------
__global__ __launch_bounds__(256) void gemm_mma(
    const float* __restrict__ A,
    const __nv_bfloat16* __restrict__ Bhi,
    const __nv_bfloat16* __restrict__ Blo,
    const float* __restrict__ bias,
    float* __restrict__ C, int Ndim)
{
    __shared__ __align__(16) __nv_bfloat16 Bs[2][2][128][40];  // [buf][plane][n][k]

    const int tid  = threadIdx.x;
    const int wid  = tid >> 5;
    const int lane = tid & 31;
    const int g    = lane >> 2;       // group id (0..7)
    const int t4   = lane & 3;        // thread in group
    const int m0   = blockIdx.y * 128;
    const int n0   = blockIdx.x * 128;
    const int wm   = (wid & 3) * 32;  // warp M offset
    const int wn   = (wid >> 2) * 64; // warp N offset

    float acc[2][8][4];
#pragma unroll
    for (int mt = 0; mt < 2; mt++)
#pragma unroll
        for (int nt = 0; nt < 8; nt++)
#pragma unroll
            for (int i = 0; i < 4; i++) acc[mt][nt][i] = 0.f;

    // B prefetch: 1024 x 16B chunks (512 per plane); 4 per thread
#define PREFETCH(s) do {                                                     \
        const int _buf = (s) & 1;                                            \
        const int _kb  = (s) * 32;                                           \
        _Pragma("unroll")                                                    \
        for (int _i = 0; _i < 4; _i++) {                                     \
            const int _id    = tid + _i * 256;                               \
            const int _plane = _id >> 9;                                     \
            const int _row   = (_id >> 2) & 127;                             \
            const int _ch    = _id & 3;                                      \
            const __nv_bfloat16* _src =                                      \
                (_plane ? Blo : Bhi) + (size_t)(n0 + _row) * CDIM + _kb + _ch * 8; \
            uint32_t _dst = smem_u32(&Bs[_buf][_plane][_row][_ch * 8]);      \
            asm volatile("cp.async.cg.shared.global [%0], [%1], 16;"         \
                         :: "r"(_dst), "l"(_src));                           \
        }                                                                    \
        asm volatile("cp.async.commit_group;" ::: "memory");                 \
    } while (0)

    PREFETCH(0);

    for (int s = 0; s < 12; s++) {
        asm volatile("cp.async.wait_group 0;" ::: "memory");
        __syncthreads();
        if (s < 11) PREFETCH(s + 1);
        const int buf = s & 1;
        const int kb  = s * 32;

#pragma unroll
        for (int kt = 0; kt < 2; kt++) {
            const int k = kb + kt * 16 + t4 * 2;
            // A fragments for both mt, split into hi/lo
            uint32_t ahi[2][4], alo[2][4];
#pragma unroll
            for (int mt = 0; mt < 2; mt++) {
                const int r0 = m0 + wm + mt * 16 + g;
                float2 p00 = *(const float2*)(A + (size_t)r0 * CDIM + k);
                float2 p10 = *(const float2*)(A + (size_t)(r0 + 8) * CDIM + k);
                float2 p01 = *(const float2*)(A + (size_t)r0 * CDIM + k + 8);
                float2 p11 = *(const float2*)(A + (size_t)(r0 + 8) * CDIM + k + 8);
                split2(p00.x, p00.y, ahi[mt][0], alo[mt][0]);
                split2(p10.x, p10.y, ahi[mt][1], alo[mt][1]);
                split2(p01.x, p01.y, ahi[mt][2], alo[mt][2]);
                split2(p11.x, p11.y, ahi[mt][3], alo[mt][3]);
            }
#pragma unroll
            for (int nt = 0; nt < 8; nt++) {
                const int bn = wn + nt * 8 + g;
                const int bk = kt * 16 + t4 * 2;
                uint32_t bh0 = *(const uint32_t*)&Bs[buf][0][bn][bk];
                uint32_t bh1 = *(const uint32_t*)&Bs[buf][0][bn][bk + 8];
                uint32_t bl0 = *(const uint32_t*)&Bs[buf][1][bn][bk];
                uint32_t bl1 = *(const uint32_t*)&Bs[buf][1][bn][bk + 8];
#pragma unroll
                for (int mt = 0; mt < 2; mt++) {
                    mma16816(acc[mt][nt], ahi[mt], bh0, bh1);
                    mma16816(acc[mt][nt], alo[mt], bh0, bh1);
                    mma16816(acc[mt][nt], ahi[mt], bl0, bl1);
                }
            }
        }
    }

    // Epilogue: bias + store
#pragma unroll
    for (int mt = 0; mt < 2; mt++) {
        const int r0 = m0 + wm + mt * 16 + g;
#pragma unroll
        for (int nt = 0; nt < 8; nt++) {
            const int col = n0 + wn + nt * 8 + t4 * 2;
            float2 bv = *(const float2*)(bias + col);
            float2 v0 = make_float2(acc[mt][nt][0] + bv.x, acc[mt][nt][1] + bv.y);
            float2 v1 = make_float2(acc[mt][nt][2] + bv.x, acc[mt][nt][3] + bv.y);
            *(float2*)(C + (size_t)r0 * Ndim + col) = v0;
            *(float2*)(C + (size_t)(r0 + 8) * Ndim + col) = v1;
        }
    }
}

// ---------------------------------------------------------------------------
// Per-window attention (fp32, unchanged — proven correct in round 1)
// ---------------------------------------------------------------------------
__global__ __launch_bounds__(256) void window_attn()
{
    const int g   = blockIdx.x;
    const int b   = g >> 8;
    const int win = g & 255;
    const int wy  = win >> 4;
    const int wx  = win & 15;

    __shared__ int tok[64];
    __shared__ float Ss[64][65];
    __shared__ __align__(16) char raw[64 * 68 * 4];
    float (*Qs)[64] = (float(*)[64])raw;
    float (*Ks)[64] = (float(*)[64])(raw + 8192);
    float (*Vs)[68] = (float(*)[68])raw;

    const int tid = threadIdx.x;
    if (tid < 64) {
        int py = tid >> 3, px = tid & 7;
        tok[tid] = b * 16384 + (wy * 8 + py) * 128 + (wx * 8 + px);
    }
    __syncthreads();

    const int tx = tid & 15;
    const int ty = tid >> 4;
    const int lr = tid & 63;
    const int lk = (tid >> 6) * 8;

    float acc[4][4];
#pragma unroll
    for (int i = 0; i < 4; i++)
#pragma unroll
        for (int j = 0; j < 4; j++) acc[i][j] = 0.f;

    const size_t rowbase = (size_t)tok[lr] * NQKV;
    for (int kt = 0; kt < CDIM; kt += 32) {
        const float* qrow = g_qkv + rowbase + kt + lk;
        float4 q0 = *(const float4*)qrow;
        float4 q1 = *(const float4*)(qrow + 4);
        const float* krow = qrow + CDIM;
        float4 k0 = *(const float4*)krow;
        float4 k1 = *(const float4*)(krow + 4);
        Qs[lk + 0][lr] = q0.x; Qs[lk + 1][lr] = q0.y;
        Qs[lk + 2][lr] = q0.z; Qs[lk + 3][lr] = q0.w;
        Qs[lk + 4][lr] = q1.x; Qs[lk + 5][lr] = q1.y;
        Qs[lk + 6][lr] = q1.z; Qs[lk + 7][lr] = q1.w;
        Ks[lk + 0][lr] = k0.x; Ks[lk + 1][lr] = k0.y;
        Ks[lk + 2][lr] = k0.z; Ks[lk + 3][lr] = k0.w;
        Ks[lk + 4][lr] = k1.x; Ks[lk + 5][lr] = k1.y;
        Ks[lk + 6][lr] = k1.z; Ks[lk + 7][lr] = k1.w;
        __syncthreads();
#pragma unroll
        for (int k = 0; k < 32; k++) {
            float4 a = *(const float4*)&Qs[k][ty * 4];
            float4 bb = *(const float4*)&Ks[k][tx * 4];
            float av[4] = {a.x, a.y, a.z, a.w};
            float bv[4] = {bb.x, bb.y, bb.z, bb.w};
#pragma unroll
            for (int i = 0; i < 4; i++)
#pragma unroll
                for (int j = 0; j < 4; j++) acc[i][j] += av[i] * bv[j];
        }
        __syncthreads();
    }
#pragma unroll
    for (int i = 0; i < 4; i++)
#pragma unroll
        for (int j = 0; j < 4; j++) Ss[ty * 4 + i][tx * 4 + j] = acc[i][j];
    __syncthreads();

    if (tid < 64) {
        float m = -1e30f;
#pragma unroll 8
        for (int j = 0; j < 64; j++) m = fmaxf(m, Ss[tid][j]);
        float s = 0.f;
#pragma unroll 8
        for (int j = 0; j < 64; j++) {
            float e = expf(Ss[tid][j] - m);
            Ss[tid][j] = e;
            s += e;
        }
        float inv = 1.f / s;
#pragma unroll 8
        for (int j = 0; j < 64; j++) Ss[tid][j] *= inv;
    }
    __syncthreads();

    const int vc = (tid >> 6) * 16;
    for (int ct = 0; ct < CDIM; ct += 64) {
        const float* vrow = g_qkv + rowbase + 2 * CDIM + ct + vc;
        float4 v0 = *(const float4*)(vrow);
        float4 v1 = *(const float4*)(vrow + 4);
        float4 v2 = *(const float4*)(vrow + 8);
        float4 v3 = *(const float4*)(vrow + 12);
        *(float4*)&Vs[lr][vc + 0]  = v0;
        *(float4*)&Vs[lr][vc + 4]  = v1;
        *(float4*)&Vs[lr][vc + 8]  = v2;
        *(float4*)&Vs[lr][vc + 12] = v3;
        __syncthreads();

        float o[4][4];
#pragma unroll
        for (int i = 0; i < 4; i++)
#pragma unroll
            for (int j = 0; j < 4; j++) o[i][j] = 0.f;
#pragma unroll
        for (int k = 0; k < 64; k++) {
            float a0 = Ss[ty * 4 + 0][k];
            float a1 = Ss[ty * 4 + 1][k];
            float a2 = Ss[ty * 4 + 2][k];
            float a3 = Ss[ty * 4 + 3][k];
            float4 bb = *(const float4*)&Vs[k][tx * 4];
            o[0][0] += a0 * bb.x; o[0][1] += a0 * bb.y; o[0][2] += a0 * bb.z; o[0][3] += a0 * bb.w;
            o[1][0] += a1 * bb.x; o[1][1] += a1 * bb.y; o[1][2] += a1 * bb.z; o[1][3] += a1 * bb.w;
            o[2][0] += a2 * bb.x; o[2][1] += a2 * bb.y; o[2][2] += a2 * bb.z; o[2][3] += a2 * bb.w;
            o[3][0] += a3 * bb.x; o[3][1] += a3 * bb.y; o[3][2] += a3 * bb.z; o[3][3] += a3 * bb.w;
        }
#pragma unroll
        for (int i = 0; i < 4; i++) {
            float* orow = g_att + (size_t)tok[ty * 4 + i] * CDIM + ct + tx * 4;
            *(float4*)orow = make_float4(o[i][0], o[i][1], o[i][2], o[i][3]);
        }
        __syncthreads();
    }
}

// ---------------------------------------------------------------------------
extern "C" void kernel_launch(void* const* d_in, const int* in_sizes, int n_in,
                              void* d_out, int out_size)
{
    const float* x      = (const float*)d_in[0];
    const float* w_qkv  = (const float*)d_in[1];
    const float* b_qkv  = (const float*)d_in[2];
    const float* w_proj = (const float*)d_in[3];
    const float* b_proj = (const float*)d_in[4];
    float* out = (float*)d_out;

    float *qkv_ptr = nullptr, *att_ptr = nullptr;
    __nv_bfloat16 *whi1 = nullptr, *wlo1 = nullptr, *whi3 = nullptr, *wlo3 = nullptr;
    cudaGetSymbolAddress((void**)&qkv_ptr, g_qkv);
    cudaGetSymbolAddress((void**)&att_ptr, g_att);
    cudaGetSymbolAddress((void**)&whi1, g_Whi1);
    cudaGetSymbolAddress((void**)&wlo1, g_Wlo1);
    cudaGetSymbolAddress((void**)&whi3, g_Whi3);
    cudaGetSymbolAddress((void**)&wlo3, g_Wlo3);

    // Weight splits (tiny)
    split_w_kernel<<<(NQKV * CDIM + 255) / 256, 256>>>(w_qkv, whi1, wlo1, NQKV);
    split_w_kernel<<<(CDIM * CDIM + 255) / 256, 256>>>(w_proj, whi3, wlo3, CDIM);

    // K1: qkv = x @ w_qkv + b_qkv
    gemm_mma<<<dim3(NQKV / 128, TOKENS / 128), 256>>>(
        x, whi1, wlo1, b_qkv, qkv_ptr, NQKV);

    // K2: per-window attention
    window_attn<<<NWIN, 256>>>();

    // K3: out = att @ w_proj + b_proj
    gemm_mma<<<dim3(CDIM / 128, TOKENS / 128), 256>>>(
        att_ptr, whi3, wlo3, b_proj, out, CDIM);
}

// round 4
// speedup vs baseline: 1.8022x; 1.0716x over previous
#include <cuda_runtime.h>
#include <cuda_bf16.h>
#include <cstdint>
#include <math.h>

// Problem constants (B=8, H=W=128, C=384, window=8)
#define TOKENS   131072              // 8*128*128
#define CDIM     384
#define NQKV     1152
#define NWIN     2048                // 8 * 16 * 16 windows

// ---------------------------------------------------------------------------
// Scratch (allocation-free rule: __device__ globals)
// ---------------------------------------------------------------------------
__device__ float          g_qkv[(size_t)TOKENS * NQKV];    // fp32 qkv (604 MB)
__device__ __nv_bfloat16  g_A2 [(size_t)TOKENS * 768];     // A split planes [hi384|lo384]
__device__ __nv_bfloat16  g_Whi1[(size_t)NQKV * CDIM];     // w_qkv^T hi  [N][K]
__device__ __nv_bfloat16  g_Wlo1[(size_t)NQKV * CDIM];     // w_qkv^T lo
__device__ __nv_bfloat16  g_Whi3[(size_t)CDIM * CDIM];     // w_proj^T hi
__device__ __nv_bfloat16  g_Wlo3[(size_t)CDIM * CDIM];     // w_proj^T lo

__device__ __forceinline__ uint32_t smem_u32(const void* p) {
    uint32_t a;
    asm("{ .reg .u64 tmp; cvta.to.shared.u64 tmp, %1; cvt.u32.u64 %0, tmp; }"
        : "=r"(a) : "l"(p));
    return a;
}

// Split a float2 into packed bf16x2 hi and lo (residual) parts.
__device__ __forceinline__ void split2(float x, float y, uint32_t& hi, uint32_t& lo) {
    uint32_t h;
    asm("cvt.rn.bf16x2.f32 %0, %1, %2;" : "=r"(h) : "f"(y), "f"(x));
    float h0 = __uint_as_float(h << 16);
    float h1 = __uint_as_float(h & 0xffff0000u);
    float r0 = x - h0, r1 = y - h1;
    asm("cvt.rn.bf16x2.f32 %0, %1, %2;" : "=r"(lo) : "f"(r1), "f"(r0));
    hi = h;
}

__device__ __forceinline__ void mma16816(float* c, const uint32_t* a,
                                         uint32_t b0, uint32_t b1) {
    asm volatile(
        "mma.sync.aligned.m16n8k16.row.col.f32.bf16.bf16.f32 "
        "{%0,%1,%2,%3}, {%4,%5,%6,%7}, {%8,%9}, {%0,%1,%2,%3};\n"
        : "+f"(c[0]), "+f"(c[1]), "+f"(c[2]), "+f"(c[3])
        : "r"(a[0]), "r"(a[1]), "r"(a[2]), "r"(a[3]), "r"(b0), "r"(b1));
}

#define LDSM_X4(r, a) \
    asm volatile("ldmatrix.sync.aligned.m8n8.x4.shared.b16 {%0,%1,%2,%3}, [%4];" \
        : "=r"((r)[0]), "=r"((r)[1]), "=r"((r)[2]), "=r"((r)[3]) : "r"(a))

// ---------------------------------------------------------------------------
// Weight split + transpose: w [384 x N] fp32 -> Whi/Wlo [N x 384] bf16
// ---------------------------------------------------------------------------
__global__ __launch_bounds__(256) void split_w_kernel(
    const float* __restrict__ w, __nv_bfloat16* __restrict__ Whi,
    __nv_bfloat16* __restrict__ Wlo, int N)
{
    const int t = blockIdx.x * 256 + threadIdx.x;
    if (t >= N * CDIM) return;
    const int n = t / CDIM;
    const int k = t % CDIM;
    const float v = w[(size_t)k * N + n];
    __nv_bfloat16 h = __float2bfloat16(v);
    __nv_bfloat16 l = __float2bfloat16(v - __bfloat162float(h));
    Whi[(size_t)n * CDIM + k] = h;
    Wlo[(size_t)n * CDIM + k] = l;
}

// ---------------------------------------------------------------------------
// Split x rows: fp32 [TOKENS][384] -> g_A2 [TOKENS][hi 384 | lo 384] bf16
// ---------------------------------------------------------------------------
__global__ __launch_bounds__(256) void split_x_kernel(
    const float* __restrict__ in, __nv_bfloat16* __restrict__ out)
{
    const int t = blockIdx.x * 256 + threadIdx.x;    // t < TOKENS*96
    const int r = t / 96;
    const int c = (t % 96) * 4;
    float4 v = *(const float4*)(in + (size_t)r * CDIM + c);
    uint32_t h0, l0, h1, l1;
    split2(v.x, v.y, h0, l0);
    split2(v.z, v.w, h1, l1);
    __nv_bfloat16* o = out + (size_t)r * 768;
    *(uint32_t*)(o + c) = h0;
    *(uint32_t*)(o + c + 2) = h1;
    *(uint32_t*)(o + 384 + c) = l0;
    *(uint32_t*)(o + 384 + c + 2) = l1;
}

// ---------------------------------------------------------------------------
// HMMA GEMM v3: C[M x Ndim] = A2 @ W^T + bias  (split-bf16, 3-pass)
//   BM=128, BN=128, BK=32, 256 threads (8 warps: 4M x 2N).
//   A2/Bhi/Blo staged via cp.async double buffer, 20-word padded rows,
//   fragments via ldmatrix.x4.
//   smem per buffer: Wa[2][128][20] + Wb[2][128][20] words = 40960 B; x2 bufs.
// ---------------------------------------------------------------------------
__global__ __launch_bounds__(256, 2) void gemm_mma(
    const __nv_bfloat16* __restrict__ A2,
    const __nv_bfloat16* __restrict__ Bhi,
    const __nv_bfloat16* __restrict__ Blo,
    const float* __restrict__ bias,
    float* __restrict__ C, int Ndim)
{
    extern __shared__ __align__(16) char smem[];
    const uint32_t smemBase = smem_u32(smem);

    const int tid  = threadIdx.x;
    const int wid  = tid >> 5;
    const int lane = tid & 31;
    const int g    = lane >> 2;
    const int t4   = lane & 3;
    const int m0   = blockIdx.y * 128;
    const int n0   = blockIdx.x * 128;
    const int wm   = (wid & 3) * 32;
    const int wn   = (wid >> 2) * 64;

    // Per-thread cp.async descriptors: 8 chunks of 16B per stage
    const __nv_bfloat16* srcs[8];
    uint32_t dsts[8];
#pragma unroll
    for (int i = 0; i < 8; i++) {
        const int id = tid + i * 256;          // < 2048
        const int ab = id >> 10;               // 0 = A, 1 = B
        const int p  = (id >> 9) & 1;
        const int r  = (id >> 2) & 127;
        const int ch = id & 3;
        if (ab == 0)
            srcs[i] = A2 + (size_t)(m0 + r) * 768 + p * 384 + ch * 8;
        else
            srcs[i] = (p ? Blo : Bhi) + (size_t)(n0 + r) * 384 + ch * 8;
        dsts[i] = smemBase + ab * 20480 + (uint32_t)(((p * 128 + r) * 20 + ch * 4) * 4);
    }

#define PREFETCH(s) do {                                                      \
        const uint32_t _boff = ((s) & 1) * 40960;                             \
        _Pragma("unroll")                                                     \
        for (int _i = 0; _i < 8; _i++) {                                      \
            asm volatile("cp.async.cg.shared.global [%0], [%1], 16;"          \
                :: "r"(dsts[_i] + _boff), "l"(srcs[_i] + (s) * 32));          \
        }                                                                     \
        asm volatile("cp.async.commit_group;" ::: "memory");                  \
    } while (0)

    // ldmatrix lane base addresses (lane&15 row, (lane>>4)*4 word offset)
    const uint32_t aAddr = smemBase +
        (uint32_t)(((wm + (lane & 15)) * 20 + ((lane >> 4) << 2)) * 4);
    const uint32_t bAddr = smemBase + 20480 +
        (uint32_t)(((wn + (lane & 15)) * 20 + ((lane >> 4) << 2)) * 4);

    float acc[2][8][4];
#pragma unroll
    for (int mt = 0; mt < 2; mt++)
#pragma unroll
        for (int nt = 0; nt < 8; nt++)
#pragma unroll
            for (int i = 0; i < 4; i++) acc[mt][nt][i] = 0.f;

    PREFETCH(0);
    PREFETCH(1);

    for (int s = 0; s < 12; s++) {
        asm volatile("cp.async.wait_group 1;" ::: "memory");
        __syncthreads();
        const uint32_t boff = (s & 1) * 40960;

#pragma unroll
        for (int kt = 0; kt < 2; kt++) {
            uint32_t ah[2][4], al[2][4];
#pragma unroll
            for (int mt = 0; mt < 2; mt++) {
                LDSM_X4(ah[mt], aAddr + boff + mt * 1280 + kt * 32);
                LDSM_X4(al[mt], aAddr + boff + 10240 + mt * 1280 + kt * 32);
            }
#pragma unroll
            for (int ntp = 0; ntp < 4; ntp++) {
                uint32_t bh[4], bl[4];
                LDSM_X4(bh, bAddr + boff + ntp * 1280 + kt * 32);
                LDSM_X4(bl, bAddr + boff + 10240 + ntp * 1280 + kt * 32);
#pragma unroll
                for (int mt = 0; mt < 2; mt++) {
                    float* c0 = acc[mt][ntp * 2];
                    float* c1 = acc[mt][ntp * 2 + 1];
                    mma16816(c0, ah[mt], bh[0], bh[2]);
                    mma16816(c0, al[mt], bh[0], bh[2]);
                    mma16816(c0, ah[mt], bl[0], bl[2]);
                    mma16816(c1, ah[mt], bh[1], bh[3]);
                    mma16816(c1, al[mt], bh[1], bh[3]);
                    mma16816(c1, ah[mt], bl[1], bl[3]);
                }
            }
        }
        __syncthreads();
        if (s + 2 < 12) PREFETCH(s + 2);
        else asm volatile("cp.async.commit_group;" ::: "memory");
    }
#undef PREFETCH

    // Epilogue: bias + store (acc[mt][ntp*2+half] -> col wn + ntp*16 + half*8 + t4*2)
#pragma unroll
    for (int mt = 0; mt < 2; mt++) {
        const int r0 = m0 + wm + mt * 16 + g;
#pragma unroll
        for (int nt = 0; nt < 8; nt++) {
            const int col = n0 + wn + (nt >> 1) * 16 + (nt & 1) * 8 + t4 * 2;
            float2 bv = *(const float2*)(bias + col);
            float2 v0 = make_float2(acc[mt][nt][0] + bv.x, acc[mt][nt][1] + bv.y);
            float2 v1 = make_float2(acc[mt][nt][2] + bv.x, acc[mt][nt][3] + bv.y);
            *(float2*)(C + (size_t)r0 * Ndim + col) = v0;
            *(float2*)(C + (size_t)(r0 + 8) * Ndim + col) = v1;
        }
    }
}

// ---------------------------------------------------------------------------
// Per-window attention (fp32; epilogue writes split-bf16 planes to g_A2)
// ---------------------------------------------------------------------------
__global__ __launch_bounds__(256) void window_attn()
{
    const int g   = blockIdx.x;
    const int b   = g >> 8;
    const int win = g & 255;
    const int wy  = win >> 4;
    const int wx  = win & 15;

    __shared__ int tok[64];
    __shared__ float Ss[64][65];
    __shared__ __align__(16) char raw[64 * 68 * 4];
    float (*Qs)[64] = (float(*)[64])raw;
    float (*Ks)[64] = (float(*)[64])(raw + 8192);
    float (*Vs)[68] = (float(*)[68])raw;

    const int tid = threadIdx.x;
    if (tid < 64) {
        int py = tid >> 3, px = tid & 7;
        tok[tid] = b * 16384 + (wy * 8 + py) * 128 + (wx * 8 + px);
    }
    __syncthreads();

    const int tx = tid & 15;
    const int ty = tid >> 4;
    const int lr = tid & 63;
    const int lk = (tid >> 6) * 8;

    float acc[4][4];
#pragma unroll
    for (int i = 0; i < 4; i++)
#pragma unroll
        for (int j = 0; j < 4; j++) acc[i][j] = 0.f;

    const size_t rowbase = (size_t)tok[lr] * NQKV;
    for (int kt = 0; kt < CDIM; kt += 32) {
        const float* qrow = g_qkv + rowbase + kt + lk;
        float4 q0 = *(const float4*)qrow;
        float4 q1 = *(const float4*)(qrow + 4);
        const float* krow = qrow + CDIM;
        float4 k0 = *(const float4*)krow;
        float4 k1 = *(const float4*)(krow + 4);
        Qs[lk + 0][lr] = q0.x; Qs[lk + 1][lr] = q0.y;
        Qs[lk + 2][lr] = q0.z; Qs[lk + 3][lr] = q0.w;
        Qs[lk + 4][lr] = q1.x; Qs[lk + 5][lr] = q1.y;
        Qs[lk + 6][lr] = q1.z; Qs[lk + 7][lr] = q1.w;
        Ks[lk + 0][lr] = k0.x; Ks[lk + 1][lr] = k0.y;
        Ks[lk + 2][lr] = k0.z; Ks[lk + 3][lr] = k0.w;
        Ks[lk + 4][lr] = k1.x; Ks[lk + 5][lr] = k1.y;
        Ks[lk + 6][lr] = k1.z; Ks[lk + 7][lr] = k1.w;
        __syncthreads();
#pragma unroll
        for (int k = 0; k < 32; k++) {
            float4 a = *(const float4*)&Qs[k][ty * 4];
            float4 bb = *(const float4*)&Ks[k][tx * 4];
            float av[4] = {a.x, a.y, a.z, a.w};
            float bv[4] = {bb.x, bb.y, bb.z, bb.w};
#pragma unroll
            for (int i = 0; i < 4; i++)
#pragma unroll
                for (int j = 0; j < 4; j++) acc[i][j] += av[i] * bv[j];
        }
        __syncthreads();
    }
#pragma unroll
    for (int i = 0; i < 4; i++)
#pragma unroll
        for (int j = 0; j < 4; j++) Ss[ty * 4 + i][tx * 4 + j] = acc[i][j];
    __syncthreads();

    if (tid < 64) {
        float m = -1e30f;
#pragma unroll 8
        for (int j = 0; j < 64; j++) m = fmaxf(m, Ss[tid][j]);
        float s = 0.f;
#pragma unroll 8
        for (int j = 0; j < 64; j++) {
            float e = expf(Ss[tid][j] - m);
            Ss[tid][j] = e;
            s += e;
        }
        float inv = 1.f / s;
#pragma unroll 8
        for (int j = 0; j < 64; j++) Ss[tid][j] *= inv;
    }
    __syncthreads();

    const int vc = (tid >> 6) * 16;
    for (int ct = 0; ct < CDIM; ct += 64) {
        const float* vrow = g_qkv + rowbase + 2 * CDIM + ct + vc;
        float4 v0 = *(const float4*)(vrow);
        float4 v1 = *(const float4*)(vrow + 4);
        float4 v2 = *(const float4*)(vrow + 8);
        float4 v3 = *(const float4*)(vrow + 12);
        *(float4*)&Vs[lr][vc + 0]  = v0;
        *(float4*)&Vs[lr][vc + 4]  = v1;
        *(float4*)&Vs[lr][vc + 8]  = v2;
        *(float4*)&Vs[lr][vc + 12] = v3;
        __syncthreads();

        float o[4][4];
#pragma unroll
        for (int i = 0; i < 4; i++)
#pragma unroll
            for (int j = 0; j < 4; j++) o[i][j] = 0.f;
#pragma unroll
        for (int k = 0; k < 64; k++) {
            float a0 = Ss[ty * 4 + 0][k];
            float a1 = Ss[ty * 4 + 1][k];
            float a2 = Ss[ty * 4 + 2][k];
            float a3 = Ss[ty * 4 + 3][k];
            float4 bb = *(const float4*)&Vs[k][tx * 4];
            o[0][0] += a0 * bb.x; o[0][1] += a0 * bb.y; o[0][2] += a0 * bb.z; o[0][3] += a0 * bb.w;
            o[1][0] += a1 * bb.x; o[1][1] += a1 * bb.y; o[1][2] += a1 * bb.z; o[1][3] += a1 * bb.w;
            o[2][0] += a2 * bb.x; o[2][1] += a2 * bb.y; o[2][2] += a2 * bb.z; o[2][3] += a2 * bb.w;
            o[3][0] += a3 * bb.x; o[3][1] += a3 * bb.y; o[3][2] += a3 * bb.z; o[3][3] += a3 * bb.w;
        }
        // Write split-bf16 planes directly into g_A2 (input of K3)
#pragma unroll
        for (int i = 0; i < 4; i++) {
            __nv_bfloat16* obase = g_A2 + (size_t)tok[ty * 4 + i] * 768 + ct + tx * 4;
            uint32_t h0, l0, h1, l1;
            split2(o[i][0], o[i][1], h0, l0);
            split2(o[i][2], o[i][3], h1, l1);
            *(uint32_t*)(obase)         = h0;
            *(uint32_t*)(obase + 2)     = h1;
            *(uint32_t*)(obase + 384)   = l0;
            *(uint32_t*)(obase + 386)   = l1;
        }
        __syncthreads();
    }
}

// ---------------------------------------------------------------------------
extern "C" void kernel_launch(void* const* d_in, const int* in_sizes, int n_in,
                              void* d_out, int out_size)
{
    const float* x      = (const float*)d_in[0];
    const float* w_qkv  = (const float*)d_in[1];
    const float* b_qkv  = (const float*)d_in[2];
    const float* w_proj = (const float*)d_in[3];
    const float* b_proj = (const float*)d_in[4];
    float* out = (float*)d_out;

    float* qkv_ptr = nullptr;
    __nv_bfloat16 *a2 = nullptr, *whi1 = nullptr, *wlo1 = nullptr,
                  *whi3 = nullptr, *wlo3 = nullptr;
    cudaGetSymbolAddress((void**)&qkv_ptr, g_qkv);
    cudaGetSymbolAddress((void**)&a2,   g_A2);
    cudaGetSymbolAddress((void**)&whi1, g_Whi1);
    cudaGetSymbolAddress((void**)&wlo1, g_Wlo1);
    cudaGetSymbolAddress((void**)&whi3, g_Whi3);
    cudaGetSymbolAddress((void**)&wlo3, g_Wlo3);

    cudaFuncSetAttribute(gemm_mma, cudaFuncAttributeMaxDynamicSharedMemorySize, 81920);

    // Weight splits (tiny)
    split_w_kernel<<<(NQKV * CDIM + 255) / 256, 256>>>(w_qkv, whi1, wlo1, NQKV);
    split_w_kernel<<<(CDIM * CDIM + 255) / 256, 256>>>(w_proj, whi3, wlo3, CDIM);

    // Split x -> A2 planes
    split_x_kernel<<<TOKENS * 96 / 256, 256>>>(x, a2);

    // K1: qkv = x @ w_qkv + b_qkv
    gemm_mma<<<dim3(NQKV / 128, TOKENS / 128), 256, 81920>>>(
        a2, whi1, wlo1, b_qkv, qkv_ptr, NQKV);

    // K2: per-window attention (writes split planes to g_A2)
    window_attn<<<NWIN, 256>>>();

    // K3: out = att @ w_proj + b_proj
    gemm_mma<<<dim3(CDIM / 128, TOKENS / 128), 256, 81920>>>(
        a2, whi3, wlo3, b_proj, out, CDIM);
}

// round 5
// speedup vs baseline: 2.0870x; 1.1580x over previous
#include <cuda_runtime.h>
#include <cuda_bf16.h>
#include <cstdint>
#include <math.h>

// Problem constants (B=8, H=W=128, C=384, window=8)
#define TOKENS   131072              // 8*128*128
#define CDIM     384
#define NQKV     1152
#define NWIN     2048                // 8 * 16 * 16 windows

// ---------------------------------------------------------------------------
// Scratch (allocation-free rule: __device__ globals)
// ---------------------------------------------------------------------------
__device__ float          g_qkv[(size_t)TOKENS * NQKV];    // fp32 qkv (604 MB)
__device__ __nv_bfloat16  g_A2 [(size_t)TOKENS * 768];     // A split planes [hi384|lo384]
__device__ __nv_bfloat16  g_Whi1[(size_t)NQKV * CDIM];     // w_qkv^T hi  [N][K]
__device__ __nv_bfloat16  g_Wlo1[(size_t)NQKV * CDIM];     // w_qkv^T lo
__device__ __nv_bfloat16  g_Whi3[(size_t)CDIM * CDIM];     // w_proj^T hi
__device__ __nv_bfloat16  g_Wlo3[(size_t)CDIM * CDIM];     // w_proj^T lo

__device__ __forceinline__ uint32_t smem_u32(const void* p) {
    uint32_t a;
    asm("{ .reg .u64 tmp; cvta.to.shared.u64 tmp, %1; cvt.u32.u64 %0, tmp; }"
        : "=r"(a) : "l"(p));
    return a;
}

// Split a float2 into packed bf16x2 hi and lo (residual) parts.
__device__ __forceinline__ void split2(float x, float y, uint32_t& hi, uint32_t& lo) {
    uint32_t h;
    asm("cvt.rn.bf16x2.f32 %0, %1, %2;" : "=r"(h) : "f"(y), "f"(x));
    float h0 = __uint_as_float(h << 16);
    float h1 = __uint_as_float(h & 0xffff0000u);
    float r0 = x - h0, r1 = y - h1;
    asm("cvt.rn.bf16x2.f32 %0, %1, %2;" : "=r"(lo) : "f"(r1), "f"(r0));
    hi = h;
}

__device__ __forceinline__ void mma16816(float* c, const uint32_t* a,
                                         uint32_t b0, uint32_t b1) {
    asm volatile(
        "mma.sync.aligned.m16n8k16.row.col.f32.bf16.bf16.f32 "
        "{%0,%1,%2,%3}, {%4,%5,%6,%7}, {%8,%9}, {%0,%1,%2,%3};\n"
        : "+f"(c[0]), "+f"(c[1]), "+f"(c[2]), "+f"(c[3])
        : "r"(a[0]), "r"(a[1]), "r"(a[2]), "r"(a[3]), "r"(b0), "r"(b1));
}

#define LDSM_X4(r, a) \
    asm volatile("ldmatrix.sync.aligned.m8n8.x4.shared.b16 {%0,%1,%2,%3}, [%4];" \
        : "=r"((r)[0]), "=r"((r)[1]), "=r"((r)[2]), "=r"((r)[3]) : "r"(a))

// ---------------------------------------------------------------------------
// Weight split + transpose: w [384 x N] fp32 -> Whi/Wlo [N x 384] bf16
// ---------------------------------------------------------------------------
__global__ __launch_bounds__(256) void split_w_kernel(
    const float* __restrict__ w, __nv_bfloat16* __restrict__ Whi,
    __nv_bfloat16* __restrict__ Wlo, int N)
{
    const int t = blockIdx.x * 256 + threadIdx.x;
    if (t >= N * CDIM) return;
    const int n = t / CDIM;
    const int k = t % CDIM;
    const float v = w[(size_t)k * N + n];
    __nv_bfloat16 h = __float2bfloat16(v);
    __nv_bfloat16 l = __float2bfloat16(v - __bfloat162float(h));
    Whi[(size_t)n * CDIM + k] = h;
    Wlo[(size_t)n * CDIM + k] = l;
}

// ---------------------------------------------------------------------------
// Split x rows: fp32 [TOKENS][384] -> g_A2 [TOKENS][hi 384 | lo 384] bf16
// ---------------------------------------------------------------------------
__global__ __launch_bounds__(256) void split_x_kernel(
    const float* __restrict__ in, __nv_bfloat16* __restrict__ out)
{
    const int t = blockIdx.x * 256 + threadIdx.x;    // t < TOKENS*96
    const int r = t / 96;
    const int c = (t % 96) * 4;
    float4 v = *(const float4*)(in + (size_t)r * CDIM + c);
    uint32_t h0, l0, h1, l1;
    split2(v.x, v.y, h0, l0);
    split2(v.z, v.w, h1, l1);
    __nv_bfloat16* o = out + (size_t)r * 768;
    *(uint32_t*)(o + c) = h0;
    *(uint32_t*)(o + c + 2) = h1;
    *(uint32_t*)(o + 384 + c) = l0;
    *(uint32_t*)(o + 384 + c + 2) = l1;
}

// ---------------------------------------------------------------------------
// HMMA GEMM v4: 3-stage cp.async pipeline, XOR-swizzled smem (no padding).
//   BM=128, BN=128, BK=32, 256 threads (8 warps: 4M x 2N), 2 CTAs/SM.
//   Stage = A[2][128][16w] + B[2][128][16w] = 32768 B; 3 stages = 98304 B.
//   Swizzle: 16B chunk ch at row r stored at ch ^ ((r>>1)&3).
// ---------------------------------------------------------------------------
#define STAGE_BYTES 32768
__global__ __launch_bounds__(256, 2) void gemm_mma(
    const __nv_bfloat16* __restrict__ A2,
    const __nv_bfloat16* __restrict__ Bhi,
    const __nv_bfloat16* __restrict__ Blo,
    const float* __restrict__ bias,
    float* __restrict__ C, int Ndim)
{
    extern __shared__ __align__(16) char smem[];
    const uint32_t smemBase = smem_u32(smem);

    const int tid  = threadIdx.x;
    const int wid  = tid >> 5;
    const int lane = tid & 31;
    const int g    = lane >> 2;
    const int t4   = lane & 3;
    const int m0   = blockIdx.y * 128;
    const int n0   = blockIdx.x * 128;
    const int wm   = (wid & 3) * 32;
    const int wn   = (wid >> 2) * 64;

    // Per-thread cp.async descriptors: 8 chunks of 16B per stage
    const __nv_bfloat16* srcs[8];
    uint32_t dsts[8];
#pragma unroll
    for (int i = 0; i < 8; i++) {
        const int id = tid + i * 256;          // < 2048
        const int ab = id >> 10;               // 0 = A, 1 = B
        const int p  = (id >> 9) & 1;
        const int r  = (id >> 2) & 127;
        const int ch = id & 3;
        if (ab == 0)
            srcs[i] = A2 + (size_t)(m0 + r) * 768 + p * 384 + ch * 8;
        else
            srcs[i] = (p ? Blo : Bhi) + (size_t)(n0 + r) * 384 + ch * 8;
        const int chs = ch ^ ((r >> 1) & 3);   // swizzled chunk
        dsts[i] = smemBase + (uint32_t)(ab * 16384 + p * 8192 + r * 64 + chs * 16);
    }

#define PREFETCH(s, off) do {                                                 \
        _Pragma("unroll")                                                     \
        for (int _i = 0; _i < 8; _i++) {                                      \
            asm volatile("cp.async.cg.shared.global [%0], [%1], 16;"          \
                :: "r"(dsts[_i] + (off)), "l"(srcs[_i] + (s) * 32));          \
        }                                                                     \
        asm volatile("cp.async.commit_group;" ::: "memory");                  \
    } while (0)

    // ldmatrix addressing: lane row = (lane&15), chunk hi bit = lane>>4,
    // per-lane constant swizzle sw = ((lane&15)>>1)&3 (tile row offsets are mult of 16).
    const int la = lane & 15;
    const int hi = lane >> 4;
    const int sw = (la >> 1) & 3;
    const uint32_t cb0 = (uint32_t)(((0 | hi) ^ sw) * 16);   // kt=0 chunk byte off
    const uint32_t cb1 = (uint32_t)(((2 | hi) ^ sw) * 16);   // kt=1 chunk byte off
    const uint32_t aRow = smemBase + (uint32_t)((wm + la) * 64);           // plane 0, mt 0
    const uint32_t bRow = smemBase + 16384 + (uint32_t)((wn + la) * 64);   // plane 0, ntp 0

    float acc[2][8][4];
#pragma unroll
    for (int mt = 0; mt < 2; mt++)
#pragma unroll
        for (int nt = 0; nt < 8; nt++)
#pragma unroll
            for (int i = 0; i < 4; i++) acc[mt][nt][i] = 0.f;

    PREFETCH(0, 0);
    PREFETCH(1, STAGE_BYTES);

    uint32_t compOff = 0;
    uint32_t pfOff   = 2 * STAGE_BYTES;

    for (int s = 0; s < 12; s++) {
        asm volatile("cp.async.wait_group 1;" ::: "memory");
        __syncthreads();
        if (s + 2 < 12) PREFETCH(s + 2, pfOff);
        else asm volatile("cp.async.commit_group;" ::: "memory");
        pfOff = (pfOff == 2 * STAGE_BYTES) ? 0 : pfOff + STAGE_BYTES;

#pragma unroll
        for (int kt = 0; kt < 2; kt++) {
            const uint32_t cb = kt ? cb1 : cb0;
            uint32_t ah[2][4], al[2][4];
#pragma unroll
            for (int mt = 0; mt < 2; mt++) {
                LDSM_X4(ah[mt], aRow + compOff + mt * 1024 + cb);
                LDSM_X4(al[mt], aRow + compOff + 8192 + mt * 1024 + cb);
            }
#pragma unroll
            for (int ntp = 0; ntp < 4; ntp++) {
                uint32_t bh[4], bl[4];
                LDSM_X4(bh, bRow + compOff + ntp * 1024 + cb);
                LDSM_X4(bl, bRow + compOff + 8192 + ntp * 1024 + cb);
#pragma unroll
                for (int mt = 0; mt < 2; mt++) {
                    float* c0 = acc[mt][ntp * 2];
                    float* c1 = acc[mt][ntp * 2 + 1];
                    mma16816(c0, ah[mt], bh[0], bh[2]);
                    mma16816(c0, al[mt], bh[0], bh[2]);
                    mma16816(c0, ah[mt], bl[0], bl[2]);
                    mma16816(c1, ah[mt], bh[1], bh[3]);
                    mma16816(c1, al[mt], bh[1], bh[3]);
                    mma16816(c1, ah[mt], bl[1], bl[3]);
                }
            }
        }
        compOff = (compOff == 2 * STAGE_BYTES) ? 0 : compOff + STAGE_BYTES;
    }
#undef PREFETCH

    // Epilogue: bias + store
#pragma unroll
    for (int mt = 0; mt < 2; mt++) {
        const int r0 = m0 + wm + mt * 16 + g;
#pragma unroll
        for (int nt = 0; nt < 8; nt++) {
            const int col = n0 + wn + (nt >> 1) * 16 + (nt & 1) * 8 + t4 * 2;
            float2 bv = *(const float2*)(bias + col);
            float2 v0 = make_float2(acc[mt][nt][0] + bv.x, acc[mt][nt][1] + bv.y);
            float2 v1 = make_float2(acc[mt][nt][2] + bv.x, acc[mt][nt][3] + bv.y);
            *(float2*)(C + (size_t)r0 * Ndim + col) = v0;
            *(float2*)(C + (size_t)(r0 + 8) * Ndim + col) = v1;
        }
    }
}

// ---------------------------------------------------------------------------
// Per-window attention (fp32 math; coalesced loads; swizzled transposed smem;
// epilogue writes split-bf16 planes to g_A2)
// ---------------------------------------------------------------------------
__global__ __launch_bounds__(256) void window_attn()
{
    const int gb  = blockIdx.x;
    const int b   = gb >> 8;
    const int win = gb & 255;
    const int wy  = win >> 4;
    const int wx  = win & 15;

    __shared__ int tok[64];
    __shared__ float Ss[64][65];
    __shared__ __align__(16) char raw[64 * 68 * 4];
    float (*Qs)[64] = (float(*)[64])raw;               // [32][64] swizzled cols
    float (*Ks)[64] = (float(*)[64])(raw + 8192);
    float (*Vs)[68] = (float(*)[68])raw;               // [64][68] overlay

    const int tid = threadIdx.x;
    if (tid < 64) {
        int py = tid >> 3, px = tid & 7;
        tok[tid] = b * 16384 + (wy * 8 + py) * 128 + (wx * 8 + px);
    }
    __syncthreads();

    const int tx  = tid & 15;
    const int ty  = tid >> 4;
    const int grp = tid >> 2;          // token index 0..63
    const int l   = tid & 3;           // lane-in-group

    const float* qb = g_qkv + (size_t)tok[grp] * NQKV;

    // ---- Phase 1: S = Q K^T ----
    float acc[4][4];
#pragma unroll
    for (int i = 0; i < 4; i++)
#pragma unroll
        for (int j = 0; j < 4; j++) acc[i][j] = 0.f;

    const int colq = grp ^ (l << 3);   // swizzled column (= grp ^ (kk&24))
    for (int kt = 0; kt < CDIM; kt += 32) {
        const float* qp = qb + kt + l * 8;
        float4 q0 = *(const float4*)qp;
        float4 q1 = *(const float4*)(qp + 4);
        float4 k0 = *(const float4*)(qp + CDIM);
        float4 k1 = *(const float4*)(qp + CDIM + 4);
        const int kk = l * 8;
        Qs[kk + 0][colq] = q0.x; Qs[kk + 1][colq] = q0.y;
        Qs[kk + 2][colq] = q0.z; Qs[kk + 3][colq] = q0.w;
        Qs[kk + 4][colq] = q1.x; Qs[kk + 5][colq] = q1.y;
        Qs[kk + 6][colq] = q1.z; Qs[kk + 7][colq] = q1.w;
        Ks[kk + 0][colq] = k0.x; Ks[kk + 1][colq] = k0.y;
        Ks[kk + 2][colq] = k0.z; Ks[kk + 3][colq] = k0.w;
        Ks[kk + 4][colq] = k1.x; Ks[kk + 5][colq] = k1.y;
        Ks[kk + 6][colq] = k1.z; Ks[kk + 7][colq] = k1.w;
        __syncthreads();
#pragma unroll
        for (int k = 0; k < 32; k++) {
            const int xv = k & 24;
            float4 a  = *(const float4*)&Qs[k][(ty * 4) ^ xv];
            float4 bb = *(const float4*)&Ks[k][(tx * 4) ^ xv];
            float av[4] = {a.x, a.y, a.z, a.w};
            float bv[4] = {bb.x, bb.y, bb.z, bb.w};
#pragma unroll
            for (int i = 0; i < 4; i++)
#pragma unroll
                for (int j = 0; j < 4; j++) acc[i][j] += av[i] * bv[j];
        }
        __syncthreads();
    }
#pragma unroll
    for (int i = 0; i < 4; i++)
#pragma unroll
        for (int j = 0; j < 4; j++) Ss[ty * 4 + i][tx * 4 + j] = acc[i][j];
    __syncthreads();

    // ---- Phase 2: softmax rows ----
    if (tid < 64) {
        float m = -1e30f;
#pragma unroll 8
        for (int j = 0; j < 64; j++) m = fmaxf(m, Ss[tid][j]);
        float s = 0.f;
#pragma unroll 8
        for (int j = 0; j < 64; j++) {
            float e = expf(Ss[tid][j] - m);
            Ss[tid][j] = e;
            s += e;
        }
        float inv = 1.f / s;
#pragma unroll 8
        for (int j = 0; j < 64; j++) Ss[tid][j] *= inv;
    }
    __syncthreads();

    // ---- Phase 3: O = P V ----
    for (int ct = 0; ct < CDIM; ct += 64) {
        const float* vp = qb + 2 * CDIM + ct;
        // u-major: lane l covers cols {4l, 16+4l, 32+4l, 48+4l} (contig 64B per token per u)
#pragma unroll
        for (int u = 0; u < 4; u++) {
            float4 v = *(const float4*)(vp + u * 16 + l * 4);
            *(float4*)&Vs[grp][u * 16 + l * 4] = v;
        }
        __syncthreads();

        float o[4][4];
#pragma unroll
        for (int i = 0; i < 4; i++)
#pragma unroll
            for (int j = 0; j < 4; j++) o[i][j] = 0.f;
#pragma unroll
        for (int k = 0; k < 64; k++) {
            float a0 = Ss[ty * 4 + 0][k];
            float a1 = Ss[ty * 4 + 1][k];
            float a2 = Ss[ty * 4 + 2][k];
            float a3 = Ss[ty * 4 + 3][k];
            float4 bb = *(const float4*)&Vs[k][tx * 4];
            o[0][0] += a0 * bb.x; o[0][1] += a0 * bb.y; o[0][2] += a0 * bb.z; o[0][3] += a0 * bb.w;
            o[1][0] += a1 * bb.x; o[1][1] += a1 * bb.y; o[1][2] += a1 * bb.z; o[1][3] += a1 * bb.w;
            o[2][0] += a2 * bb.x; o[2][1] += a2 * bb.y; o[2][2] += a2 * bb.z; o[2][3] += a2 * bb.w;
            o[3][0] += a3 * bb.x; o[3][1] += a3 * bb.y; o[3][2] += a3 * bb.z; o[3][3] += a3 * bb.w;
        }
        // Write split-bf16 planes directly into g_A2 (input of K3)
#pragma unroll
        for (int i = 0; i < 4; i++) {
            __nv_bfloat16* obase = g_A2 + (size_t)tok[ty * 4 + i] * 768 + ct + tx * 4;
            uint32_t h0, l0, h1, l1;
            split2(o[i][0], o[i][1], h0, l0);
            split2(o[i][2], o[i][3], h1, l1);
            *(uint32_t*)(obase)         = h0;
            *(uint32_t*)(obase + 2)     = h1;
            *(uint32_t*)(obase + 384)   = l0;
            *(uint32_t*)(obase + 386)   = l1;
        }
        __syncthreads();
    }
}

// ---------------------------------------------------------------------------
extern "C" void kernel_launch(void* const* d_in, const int* in_sizes, int n_in,
                              void* d_out, int out_size)
{
    const float* x      = (const float*)d_in[0];
    const float* w_qkv  = (const float*)d_in[1];
    const float* b_qkv  = (const float*)d_in[2];
    const float* w_proj = (const float*)d_in[3];
    const float* b_proj = (const float*)d_in[4];
    float* out = (float*)d_out;

    float* qkv_ptr = nullptr;
    __nv_bfloat16 *a2 = nullptr, *whi1 = nullptr, *wlo1 = nullptr,
                  *whi3 = nullptr, *wlo3 = nullptr;
    cudaGetSymbolAddress((void**)&qkv_ptr, g_qkv);
    cudaGetSymbolAddress((void**)&a2,   g_A2);
    cudaGetSymbolAddress((void**)&whi1, g_Whi1);
    cudaGetSymbolAddress((void**)&wlo1, g_Wlo1);
    cudaGetSymbolAddress((void**)&whi3, g_Whi3);
    cudaGetSymbolAddress((void**)&wlo3, g_Wlo3);

    cudaFuncSetAttribute(gemm_mma, cudaFuncAttributeMaxDynamicSharedMemorySize,
                         3 * STAGE_BYTES);

    // Weight splits (tiny)
    split_w_kernel<<<(NQKV * CDIM + 255) / 256, 256>>>(w_qkv, whi1, wlo1, NQKV);
    split_w_kernel<<<(CDIM * CDIM + 255) / 256, 256>>>(w_proj, whi3, wlo3, CDIM);

    // Split x -> A2 planes
    split_x_kernel<<<TOKENS * 96 / 256, 256>>>(x, a2);

    // K1: qkv = x @ w_qkv + b_qkv
    gemm_mma<<<dim3(NQKV / 128, TOKENS / 128), 256, 3 * STAGE_BYTES>>>(
        a2, whi1, wlo1, b_qkv, qkv_ptr, NQKV);

    // K2: per-window attention (writes split planes to g_A2)
    window_attn<<<NWIN, 256>>>();

    // K3: out = att @ w_proj + b_proj
    gemm_mma<<<dim3(CDIM / 128, TOKENS / 128), 256, 3 * STAGE_BYTES>>>(
        a2, whi3, wlo3, b_proj, out, CDIM);
}

// round 6
// speedup vs baseline: 2.1907x; 1.0497x over previous
#include <cuda_runtime.h>
#include <cuda_bf16.h>
#include <cstdint>
#include <math.h>

// Problem constants (B=8, H=W=128, C=384, window=8)
#define TOKENS   131072              // 8*128*128
#define CDIM     384
#define NQKV     1152
#define NWIN     2048                // 8 * 16 * 16 windows

// ---------------------------------------------------------------------------
// Scratch (allocation-free rule: __device__ globals)
// ---------------------------------------------------------------------------
__device__ float          g_qkv[(size_t)TOKENS * NQKV];    // fp32 qkv (604 MB)
__device__ __nv_bfloat16  g_A2 [(size_t)TOKENS * 768];     // A split planes [hi384|lo384]
__device__ __nv_bfloat16  g_Whi1[(size_t)NQKV * CDIM];     // w_qkv^T hi  [N][K]
__device__ __nv_bfloat16  g_Wlo1[(size_t)NQKV * CDIM];     // w_qkv^T lo
__device__ __nv_bfloat16  g_Whi3[(size_t)CDIM * CDIM];     // w_proj^T hi
__device__ __nv_bfloat16  g_Wlo3[(size_t)CDIM * CDIM];     // w_proj^T lo

__device__ __forceinline__ uint32_t smem_u32(const void* p) {
    uint32_t a;
    asm("{ .reg .u64 tmp; cvta.to.shared.u64 tmp, %1; cvt.u32.u64 %0, tmp; }"
        : "=r"(a) : "l"(p));
    return a;
}

// Split a float2 into packed bf16x2 hi and lo (residual) parts.
__device__ __forceinline__ void split2(float x, float y, uint32_t& hi, uint32_t& lo) {
    uint32_t h;
    asm("cvt.rn.bf16x2.f32 %0, %1, %2;" : "=r"(h) : "f"(y), "f"(x));
    float h0 = __uint_as_float(h << 16);
    float h1 = __uint_as_float(h & 0xffff0000u);
    float r0 = x - h0, r1 = y - h1;
    asm("cvt.rn.bf16x2.f32 %0, %1, %2;" : "=r"(lo) : "f"(r1), "f"(r0));
    hi = h;
}

__device__ __forceinline__ void mma16816(float* c, const uint32_t* a,
                                         uint32_t b0, uint32_t b1) {
    asm volatile(
        "mma.sync.aligned.m16n8k16.row.col.f32.bf16.bf16.f32 "
        "{%0,%1,%2,%3}, {%4,%5,%6,%7}, {%8,%9}, {%0,%1,%2,%3};\n"
        : "+f"(c[0]), "+f"(c[1]), "+f"(c[2]), "+f"(c[3])
        : "r"(a[0]), "r"(a[1]), "r"(a[2]), "r"(a[3]), "r"(b0), "r"(b1));
}

#define LDSM_X4(r, a) \
    asm volatile("ldmatrix.sync.aligned.m8n8.x4.shared.b16 {%0,%1,%2,%3}, [%4];" \
        : "=r"((r)[0]), "=r"((r)[1]), "=r"((r)[2]), "=r"((r)[3]) : "r"(a))

// ---------------------------------------------------------------------------
// Weight split + transpose: w [384 x N] fp32 -> Whi/Wlo [N x 384] bf16
// ---------------------------------------------------------------------------
__global__ __launch_bounds__(256) void split_w_kernel(
    const float* __restrict__ w, __nv_bfloat16* __restrict__ Whi,
    __nv_bfloat16* __restrict__ Wlo, int N)
{
    const int t = blockIdx.x * 256 + threadIdx.x;
    if (t >= N * CDIM) return;
    const int n = t / CDIM;
    const int k = t % CDIM;
    const float v = w[(size_t)k * N + n];
    __nv_bfloat16 h = __float2bfloat16(v);
    __nv_bfloat16 l = __float2bfloat16(v - __bfloat162float(h));
    Whi[(size_t)n * CDIM + k] = h;
    Wlo[(size_t)n * CDIM + k] = l;
}

// ---------------------------------------------------------------------------
// Split x rows: fp32 [TOKENS][384] -> g_A2 [TOKENS][hi 384 | lo 384] bf16
// ---------------------------------------------------------------------------
__global__ __launch_bounds__(256) void split_x_kernel(
    const float* __restrict__ in, __nv_bfloat16* __restrict__ out)
{
    const int t = blockIdx.x * 256 + threadIdx.x;    // t < TOKENS*96
    const int r = t / 96;
    const int c = (t % 96) * 4;
    float4 v = *(const float4*)(in + (size_t)r * CDIM + c);
    uint32_t h0, l0, h1, l1;
    split2(v.x, v.y, h0, l0);
    split2(v.z, v.w, h1, l1);
    __nv_bfloat16* o = out + (size_t)r * 768;
    *(uint32_t*)(o + c) = h0;
    *(uint32_t*)(o + c + 2) = h1;
    *(uint32_t*)(o + 384 + c) = l0;
    *(uint32_t*)(o + 384 + c + 2) = l1;
}

// ---------------------------------------------------------------------------
// HMMA GEMM v5: fully-unrolled 12-stage pipeline (3 bufs), immediate offsets,
// pass-major MMA ordering (dependency distance 4).
//   BM=128, BN=128, BK=32, 256 threads (8 warps: 4M x 2N), 2 CTAs/SM.
//   Stage = A[2][128][16w] + B[2][128][16w] = 32768 B; 3 stages = 98304 B.
//   Swizzle: 16B chunk ch at row r stored at ch ^ ((r>>1)&3).
// ---------------------------------------------------------------------------
#define STAGE_BYTES 32768u
__global__ __launch_bounds__(256, 2) void gemm_mma(
    const __nv_bfloat16* __restrict__ A2,
    const __nv_bfloat16* __restrict__ Bhi,
    const __nv_bfloat16* __restrict__ Blo,
    const float* __restrict__ bias,
    float* __restrict__ C, int Ndim)
{
    extern __shared__ __align__(16) char smem[];
    const uint32_t smemBase = smem_u32(smem);

    const int tid  = threadIdx.x;
    const int wid  = tid >> 5;
    const int lane = tid & 31;
    const int g    = lane >> 2;
    const int t4   = lane & 3;
    const int m0   = blockIdx.y * 128;
    const int n0   = blockIdx.x * 128;
    const int wm   = (wid & 3) * 32;
    const int wn   = (wid >> 2) * 64;

    // Per-thread cp.async descriptors: 8 chunks of 16B per stage
    const __nv_bfloat16* srcs[8];
    uint32_t dsts[8];
#pragma unroll
    for (int i = 0; i < 8; i++) {
        const int id = tid + i * 256;          // < 2048
        const int ab = id >> 10;               // 0 = A, 1 = B
        const int p  = (id >> 9) & 1;
        const int r  = (id >> 2) & 127;
        const int ch = id & 3;
        if (ab == 0)
            srcs[i] = A2 + (size_t)(m0 + r) * 768 + p * 384 + ch * 8;
        else
            srcs[i] = (p ? Blo : Bhi) + (size_t)(n0 + r) * 384 + ch * 8;
        const int chs = ch ^ ((r >> 1) & 3);   // swizzled chunk
        dsts[i] = smemBase + (uint32_t)(ab * 16384 + p * 8192 + r * 64 + chs * 16);
    }

#define PREFETCH(s, off) do {                                                 \
        _Pragma("unroll")                                                     \
        for (int _i = 0; _i < 8; _i++) {                                      \
            asm volatile("cp.async.cg.shared.global [%0], [%1], 16;"          \
                :: "r"(dsts[_i] + (off)), "l"(srcs[_i] + (s) * 32));          \
        }                                                                     \
        asm volatile("cp.async.commit_group;" ::: "memory");                  \
    } while (0)

    // ldmatrix addressing: lane row = (lane&15), chunk hi bit = lane>>4,
    // per-lane constant swizzle sw = ((lane&15)>>1)&3.
    const int la = lane & 15;
    const int hi = lane >> 4;
    const int sw = (la >> 1) & 3;
    const uint32_t cb0 = (uint32_t)(((0 | hi) ^ sw) * 16);   // kt=0 chunk byte off
    const uint32_t cb1 = (uint32_t)(((2 | hi) ^ sw) * 16);   // kt=1 chunk byte off
    // Fused base addresses (A plane0 @0, B plane0 @16384; lo planes +8192)
    const uint32_t aA[2] = { smemBase + (uint32_t)((wm + la) * 64) + cb0,
                             smemBase + (uint32_t)((wm + la) * 64) + cb1 };
    const uint32_t bA[2] = { smemBase + 16384 + (uint32_t)((wn + la) * 64) + cb0,
                             smemBase + 16384 + (uint32_t)((wn + la) * 64) + cb1 };

    float acc[2][8][4];
#pragma unroll
    for (int mt = 0; mt < 2; mt++)
#pragma unroll
        for (int nt = 0; nt < 8; nt++)
#pragma unroll
            for (int i = 0; i < 4; i++) acc[mt][nt][i] = 0.f;

    PREFETCH(0, 0);
    PREFETCH(1, STAGE_BYTES);

#pragma unroll
    for (int s = 0; s < 12; s++) {
        asm volatile("cp.async.wait_group 1;" ::: "memory");
        __syncthreads();
        if (s < 10) PREFETCH(s + 2, ((s + 2) % 3) * STAGE_BYTES);
        else asm volatile("cp.async.commit_group;" ::: "memory");
        const uint32_t off = (s % 3) * STAGE_BYTES;   // compile-time per iter

#pragma unroll
        for (int kt = 0; kt < 2; kt++) {
            uint32_t ah[2][4], al[2][4];
#pragma unroll
            for (int mt = 0; mt < 2; mt++) {
                LDSM_X4(ah[mt], aA[kt] + off + mt * 1024);
                LDSM_X4(al[mt], aA[kt] + off + 8192 + mt * 1024);
            }
#pragma unroll
            for (int ntp = 0; ntp < 4; ntp++) {
                uint32_t bh[4], bl[4];
                LDSM_X4(bh, bA[kt] + off + ntp * 1024);
                LDSM_X4(bl, bA[kt] + off + 8192 + ntp * 1024);
                float* c00 = acc[0][ntp * 2];
                float* c01 = acc[0][ntp * 2 + 1];
                float* c10 = acc[1][ntp * 2];
                float* c11 = acc[1][ntp * 2 + 1];
                // pass hi*hi (4 independent accs)
                mma16816(c00, ah[0], bh[0], bh[2]);
                mma16816(c01, ah[0], bh[1], bh[3]);
                mma16816(c10, ah[1], bh[0], bh[2]);
                mma16816(c11, ah[1], bh[1], bh[3]);
                // pass lo*hi
                mma16816(c00, al[0], bh[0], bh[2]);
                mma16816(c01, al[0], bh[1], bh[3]);
                mma16816(c10, al[1], bh[0], bh[2]);
                mma16816(c11, al[1], bh[1], bh[3]);
                // pass hi*lo
                mma16816(c00, ah[0], bl[0], bl[2]);
                mma16816(c01, ah[0], bl[1], bl[3]);
                mma16816(c10, ah[1], bl[0], bl[2]);
                mma16816(c11, ah[1], bl[1], bl[3]);
            }
        }
    }
#undef PREFETCH

    // Epilogue: bias + store
#pragma unroll
    for (int mt = 0; mt < 2; mt++) {
        const int r0 = m0 + wm + mt * 16 + g;
#pragma unroll
        for (int nt = 0; nt < 8; nt++) {
            const int col = n0 + wn + (nt >> 1) * 16 + (nt & 1) * 8 + t4 * 2;
            float2 bv = *(const float2*)(bias + col);
            float2 v0 = make_float2(acc[mt][nt][0] + bv.x, acc[mt][nt][1] + bv.y);
            float2 v1 = make_float2(acc[mt][nt][2] + bv.x, acc[mt][nt][3] + bv.y);
            *(float2*)(C + (size_t)r0 * Ndim + col) = v0;
            *(float2*)(C + (size_t)(r0 + 8) * Ndim + col) = v1;
        }
    }
}

// ---------------------------------------------------------------------------
// Per-window attention (fp32 math; coalesced loads; swizzled transposed smem;
// epilogue writes split-bf16 planes to g_A2)
// ---------------------------------------------------------------------------
__global__ __launch_bounds__(256) void window_attn()
{
    const int gb  = blockIdx.x;
    const int b   = gb >> 8;
    const int win = gb & 255;
    const int wy  = win >> 4;
    const int wx  = win & 15;

    __shared__ int tok[64];
    __shared__ float Ss[64][65];
    __shared__ __align__(16) char raw[64 * 68 * 4];
    float (*Qs)[64] = (float(*)[64])raw;               // [32][64] swizzled cols
    float (*Ks)[64] = (float(*)[64])(raw + 8192);
    float (*Vs)[68] = (float(*)[68])raw;               // [64][68] overlay

    const int tid = threadIdx.x;
    if (tid < 64) {
        int py = tid >> 3, px = tid & 7;
        tok[tid] = b * 16384 + (wy * 8 + py) * 128 + (wx * 8 + px);
    }
    __syncthreads();

    const int tx  = tid & 15;
    const int ty  = tid >> 4;
    const int grp = tid >> 2;          // token index 0..63
    const int l   = tid & 3;           // lane-in-group

    const float* qb = g_qkv + (size_t)tok[grp] * NQKV;

    // ---- Phase 1: S = Q K^T ----
    float acc[4][4];
#pragma unroll
    for (int i = 0; i < 4; i++)
#pragma unroll
        for (int j = 0; j < 4; j++) acc[i][j] = 0.f;

    const int colq = grp ^ (l << 3);   // swizzled column (= grp ^ (kk&24))
    for (int kt = 0; kt < CDIM; kt += 32) {
        const float* qp = qb + kt + l * 8;
        float4 q0 = *(const float4*)qp;
        float4 q1 = *(const float4*)(qp + 4);
        float4 k0 = *(const float4*)(qp + CDIM);
        float4 k1 = *(const float4*)(qp + CDIM + 4);
        const int kk = l * 8;
        Qs[kk + 0][colq] = q0.x; Qs[kk + 1][colq] = q0.y;
        Qs[kk + 2][colq] = q0.z; Qs[kk + 3][colq] = q0.w;
        Qs[kk + 4][colq] = q1.x; Qs[kk + 5][colq] = q1.y;
        Qs[kk + 6][colq] = q1.z; Qs[kk + 7][colq] = q1.w;
        Ks[kk + 0][colq] = k0.x; Ks[kk + 1][colq] = k0.y;
        Ks[kk + 2][colq] = k0.z; Ks[kk + 3][colq] = k0.w;
        Ks[kk + 4][colq] = k1.x; Ks[kk + 5][colq] = k1.y;
        Ks[kk + 6][colq] = k1.z; Ks[kk + 7][colq] = k1.w;
        __syncthreads();
#pragma unroll
        for (int k = 0; k < 32; k++) {
            const int xv = k & 24;
            float4 a  = *(const float4*)&Qs[k][(ty * 4) ^ xv];
            float4 bb = *(const float4*)&Ks[k][(tx * 4) ^ xv];
            float av[4] = {a.x, a.y, a.z, a.w};
            float bv[4] = {bb.x, bb.y, bb.z, bb.w};
#pragma unroll
            for (int i = 0; i < 4; i++)
#pragma unroll
                for (int j = 0; j < 4; j++) acc[i][j] += av[i] * bv[j];
        }
        __syncthreads();
    }
#pragma unroll
    for (int i = 0; i < 4; i++)
#pragma unroll
        for (int j = 0; j < 4; j++) Ss[ty * 4 + i][tx * 4 + j] = acc[i][j];
    __syncthreads();

    // ---- Phase 2: softmax rows ----
    if (tid < 64) {
        float m = -1e30f;
#pragma unroll 8
        for (int j = 0; j < 64; j++) m = fmaxf(m, Ss[tid][j]);
        float s = 0.f;
#pragma unroll 8
        for (int j = 0; j < 64; j++) {
            float e = expf(Ss[tid][j] - m);
            Ss[tid][j] = e;
            s += e;
        }
        float inv = 1.f / s;
#pragma unroll 8
        for (int j = 0; j < 64; j++) Ss[tid][j] *= inv;
    }
    __syncthreads();

    // ---- Phase 3: O = P V ----
    for (int ct = 0; ct < CDIM; ct += 64) {
        const float* vp = qb + 2 * CDIM + ct;
#pragma unroll
        for (int u = 0; u < 4; u++) {
            float4 v = *(const float4*)(vp + u * 16 + l * 4);
            *(float4*)&Vs[grp][u * 16 + l * 4] = v;
        }
        __syncthreads();

        float o[4][4];
#pragma unroll
        for (int i = 0; i < 4; i++)
#pragma unroll
            for (int j = 0; j < 4; j++) o[i][j] = 0.f;
#pragma unroll
        for (int k = 0; k < 64; k++) {
            float a0 = Ss[ty * 4 + 0][k];
            float a1 = Ss[ty * 4 + 1][k];
            float a2 = Ss[ty * 4 + 2][k];
            float a3 = Ss[ty * 4 + 3][k];
            float4 bb = *(const float4*)&Vs[k][tx * 4];
            o[0][0] += a0 * bb.x; o[0][1] += a0 * bb.y; o[0][2] += a0 * bb.z; o[0][3] += a0 * bb.w;
            o[1][0] += a1 * bb.x; o[1][1] += a1 * bb.y; o[1][2] += a1 * bb.z; o[1][3] += a1 * bb.w;
            o[2][0] += a2 * bb.x; o[2][1] += a2 * bb.y; o[2][2] += a2 * bb.z; o[2][3] += a2 * bb.w;
            o[3][0] += a3 * bb.x; o[3][1] += a3 * bb.y; o[3][2] += a3 * bb.z; o[3][3] += a3 * bb.w;
        }
        // Write split-bf16 planes directly into g_A2 (input of K3)
#pragma unroll
        for (int i = 0; i < 4; i++) {
            __nv_bfloat16* obase = g_A2 + (size_t)tok[ty * 4 + i] * 768 + ct + tx * 4;
            uint32_t h0, l0, h1, l1;
            split2(o[i][0], o[i][1], h0, l0);
            split2(o[i][2], o[i][3], h1, l1);
            *(uint32_t*)(obase)         = h0;
            *(uint32_t*)(obase + 2)     = h1;
            *(uint32_t*)(obase + 384)   = l0;
            *(uint32_t*)(obase + 386)   = l1;
        }
        __syncthreads();
    }
}

// ---------------------------------------------------------------------------
extern "C" void kernel_launch(void* const* d_in, const int* in_sizes, int n_in,
                              void* d_out, int out_size)
{
    const float* x      = (const float*)d_in[0];
    const float* w_qkv  = (const float*)d_in[1];
    const float* b_qkv  = (const float*)d_in[2];
    const float* w_proj = (const float*)d_in[3];
    const float* b_proj = (const float*)d_in[4];
    float* out = (float*)d_out;

    float* qkv_ptr = nullptr;
    __nv_bfloat16 *a2 = nullptr, *whi1 = nullptr, *wlo1 = nullptr,
                  *whi3 = nullptr, *wlo3 = nullptr;
    cudaGetSymbolAddress((void**)&qkv_ptr, g_qkv);
    cudaGetSymbolAddress((void**)&a2,   g_A2);
    cudaGetSymbolAddress((void**)&whi1, g_Whi1);
    cudaGetSymbolAddress((void**)&wlo1, g_Wlo1);
    cudaGetSymbolAddress((void**)&whi3, g_Whi3);
    cudaGetSymbolAddress((void**)&wlo3, g_Wlo3);

    cudaFuncSetAttribute(gemm_mma, cudaFuncAttributeMaxDynamicSharedMemorySize,
                         3 * STAGE_BYTES);

    // Weight splits (tiny)
    split_w_kernel<<<(NQKV * CDIM + 255) / 256, 256>>>(w_qkv, whi1, wlo1, NQKV);
    split_w_kernel<<<(CDIM * CDIM + 255) / 256, 256>>>(w_proj, whi3, wlo3, CDIM);

    // Split x -> A2 planes
    split_x_kernel<<<TOKENS * 96 / 256, 256>>>(x, a2);

    // K1: qkv = x @ w_qkv + b_qkv
    gemm_mma<<<dim3(NQKV / 128, TOKENS / 128), 256, 3 * STAGE_BYTES>>>(
        a2, whi1, wlo1, b_qkv, qkv_ptr, NQKV);

    // K2: per-window attention (writes split planes to g_A2)
    window_attn<<<NWIN, 256>>>();

    // K3: out = att @ w_proj + b_proj
    gemm_mma<<<dim3(CDIM / 128, TOKENS / 128), 256, 3 * STAGE_BYTES>>>(
        a2, whi3, wlo3, b_proj, out, CDIM);
}